// round 5
// baseline (speedup 1.0000x reference)
#include <cuda_runtime.h>
#include <cuda_bf16.h>

// SegmentalEmotion: per-sample sliding-window segment means (2-kernel).
// H: [B, T, D] fp32, lengths_sec: [B] fp32.
// Output: S_pad [B, maxS, D] fp32 (+ mask [B, maxS] fp32 appended, auto-detect).
//
// Plan (matches numpy fp64 bit-for-bit):
//   dur = max(len, 0.001); fps = T/dur
//   win = max(1, rint(fps)); hop = max(1, rint(fps*0.5))
//   n = (T >= win) ? (T-win)/hop + 1 : 0 ; n==0 -> fallback full-T mean
//
// Phase 1 (piece_sum): hop-chunks split into <=4 uniform pieces (~19-38
//   frames); each block handles 2 linear piece slots; computes the plan once
//   per block (amortized over long memory work) and block m==0 publishes the
//   plan ints to g_plan for phase 2. Reads H exactly once, streaming loads.
// Phase 2 (seg_out): plan from g_plan (cheap LDG, no fp64); window s =
//   pieces of chunk s + chunk s+1 (+/- <=1 edge frame), scale 1/win, write
//   output + mask.

#define T_FRAMES 1500
#define D_DIM    768
#define D_VEC    (D_DIM / 4)   // 192 float4 lanes
#define NTHREADS 192
#define MAX_B    32
#define MAX_NHOP 60            // ceil(1500/25)
#define MAX_NP   4
#define PG       40            // phase-1 grid.x; each block does slots m, m+PG
#define MAX_PIECES 80          // >= max nhop*np (78 @ hop~39)
#define PIECE_TGT 38           // target frames per piece

// piece sums: P[b, j, p, :]
__device__ float g_P[(size_t)MAX_B * MAX_NHOP * MAX_NP * D_DIM];
// plan[b]: {win, hop, n_eff, nhop, np, fallback, pad, pad}
__device__ int g_plan[MAX_B][8];

struct Plan { int win, hop, n_eff, nhop, np, plen, fallback; };

// fp64 plan — call from ONE thread per block only.
__device__ __forceinline__ Plan compute_plan(float len)
{
    Plan p;
    double dur = fmax((double)len, 0.001);
    double fps = (double)T_FRAMES / dur;
    long long win = llrint(fps);        if (win < 1) win = 1;   // WIN_SEC = 1.0
    long long hop = llrint(fps * 0.5);  if (hop < 1) hop = 1;   // HOP_SEC = 0.5
    long long n = ((long long)T_FRAMES >= win)
                      ? ((long long)T_FRAMES - win) / hop + 1 : 0;
    p.fallback = (n == 0);
    if (win > T_FRAMES + 1) win = T_FRAMES + 1;   // unused when fallback
    if (hop > T_FRAMES) hop = T_FRAMES;
    p.win   = (int)win;
    p.hop   = (int)hop;
    p.n_eff = (int)(p.fallback ? 1 : n);
    p.nhop  = (T_FRAMES + p.hop - 1) / p.hop;
    int np = (p.hop + PIECE_TGT - 1) / PIECE_TGT;
    if (np > MAX_NP) np = MAX_NP;
    p.np   = np;
    p.plen = (p.hop + np - 1) / np;
    return p;
}

// ---------- Phase 1: uniform piece sums, reads H exactly once ----------
__global__ __launch_bounds__(NTHREADS)
void piece_sum_kernel(const float* __restrict__ H,
                      const float* __restrict__ lens)
{
    const int b   = blockIdx.y;
    const int tid = threadIdx.x;

    __shared__ Plan sp;
    if (tid == 0) {
        sp = compute_plan(lens[b]);
        if (blockIdx.x == 0) {   // publish plan for phase 2
            g_plan[b][0] = sp.win;
            g_plan[b][1] = sp.hop;
            g_plan[b][2] = sp.n_eff;
            g_plan[b][3] = sp.nhop;
            g_plan[b][4] = sp.np;
            g_plan[b][5] = sp.fallback;
        }
    }
    __syncthreads();

    const int np      = sp.np;
    const int hop     = sp.hop;
    const int plen    = sp.plen;
    const int npieces = sp.nhop * np;

    const float4* __restrict__ Hb =
        (const float4*)H + (size_t)b * T_FRAMES * D_VEC + tid;

    #pragma unroll
    for (int iter = 0; iter < 2; ++iter) {
        const int m = blockIdx.x + iter * PG;    // linear (chunk, piece) slot
        if (m >= npieces) break;
        const int j = m / np;
        const int p = m - j * np;

        int t0 = j * hop + p * plen;
        int chunk_end = j * hop + hop;
        if (chunk_end > T_FRAMES) chunk_end = T_FRAMES;
        int t1 = t0 + plen;
        if (t1 > chunk_end) t1 = chunk_end;

        float4 acc = make_float4(0.f, 0.f, 0.f, 0.f);
        int t = t0;
        for (; t + 8 <= t1; t += 8) {
            float4 v0 = __ldcs(&Hb[(t + 0) * D_VEC]);
            float4 v1 = __ldcs(&Hb[(t + 1) * D_VEC]);
            float4 v2 = __ldcs(&Hb[(t + 2) * D_VEC]);
            float4 v3 = __ldcs(&Hb[(t + 3) * D_VEC]);
            float4 v4 = __ldcs(&Hb[(t + 4) * D_VEC]);
            float4 v5 = __ldcs(&Hb[(t + 5) * D_VEC]);
            float4 v6 = __ldcs(&Hb[(t + 6) * D_VEC]);
            float4 v7 = __ldcs(&Hb[(t + 7) * D_VEC]);
            acc.x += v0.x + v1.x + v2.x + v3.x + v4.x + v5.x + v6.x + v7.x;
            acc.y += v0.y + v1.y + v2.y + v3.y + v4.y + v5.y + v6.y + v7.y;
            acc.z += v0.z + v1.z + v2.z + v3.z + v4.z + v5.z + v6.z + v7.z;
            acc.w += v0.w + v1.w + v2.w + v3.w + v4.w + v5.w + v6.w + v7.w;
        }
        for (; t < t1; ++t) {
            float4 v = __ldcs(&Hb[t * D_VEC]);
            acc.x += v.x; acc.y += v.y; acc.z += v.z; acc.w += v.w;
        }

        ((float4*)g_P)[(((size_t)b * MAX_NHOP + j) * MAX_NP + p) * D_VEC + tid] = acc;
    }
}

// ---------- Phase 2: combine piece sums + edge correction ----------
__global__ __launch_bounds__(NTHREADS)
void seg_out_kernel(const float* __restrict__ H,
                    float* __restrict__ S,      // [B, maxS, D]
                    float* __restrict__ Mout,   // [B, maxS] or nullptr
                    int maxS)
{
    const int s   = blockIdx.x;
    const int b   = blockIdx.y;
    const int tid = threadIdx.x;

    const int win      = __ldg(&g_plan[b][0]);
    const int hop      = __ldg(&g_plan[b][1]);
    const int n_eff    = __ldg(&g_plan[b][2]);
    const int nhop     = __ldg(&g_plan[b][3]);
    const int np       = __ldg(&g_plan[b][4]);
    const int fallback = __ldg(&g_plan[b][5]);

    float4* outRow = (float4*)(S + ((size_t)b * maxS + s) * D_DIM);

    if (s >= n_eff) {
        outRow[tid] = make_float4(0.f, 0.f, 0.f, 0.f);
        if (Mout != nullptr && tid == 0)
            Mout[(size_t)b * maxS + s] = 0.f;
        return;
    }

    const float4* __restrict__ Pb =
        (const float4*)g_P + (size_t)b * MAX_NHOP * MAX_NP * D_VEC + tid;
    const float4* __restrict__ Hb =
        (const float4*)H + (size_t)b * T_FRAMES * D_VEC + tid;

    float4 acc = make_float4(0.f, 0.f, 0.f, 0.f);
    int cnt;

    if (fallback) {
        for (int j = 0; j < nhop; ++j)
            for (int p = 0; p < np; ++p) {
                float4 v = Pb[((size_t)j * MAX_NP + p) * D_VEC];
                acc.x += v.x; acc.y += v.y; acc.z += v.z; acc.w += v.w;
            }
        cnt = T_FRAMES;
    } else {
        const int start = s * hop;
        const int end   = start + win;           // <= T by definition of n
        const bool have2 = (s + 1) < nhop;

        #pragma unroll
        for (int p = 0; p < MAX_NP; ++p) {
            if (p < np) {
                float4 v = Pb[((size_t)s * MAX_NP + p) * D_VEC];
                acc.x += v.x; acc.y += v.y; acc.z += v.z; acc.w += v.w;
            }
        }
        if (have2) {
            #pragma unroll
            for (int p = 0; p < MAX_NP; ++p) {
                if (p < np) {
                    float4 v = Pb[((size_t)(s + 1) * MAX_NP + p) * D_VEC];
                    acc.x += v.x; acc.y += v.y; acc.z += v.z; acc.w += v.w;
                }
            }
        }
        // chunks s (+ s+1) cover [start, cov_end)
        int cov_end = start + (have2 ? 2 : 1) * hop;
        if (cov_end > T_FRAMES) cov_end = T_FRAMES;

        for (int t = cov_end; t < end; ++t) {     // add missing (<=1 in practice)
            float4 v = Hb[t * D_VEC];
            acc.x += v.x; acc.y += v.y; acc.z += v.z; acc.w += v.w;
        }
        for (int t = end; t < cov_end; ++t) {     // subtract excess (<=1)
            float4 v = Hb[t * D_VEC];
            acc.x -= v.x; acc.y -= v.y; acc.z -= v.z; acc.w -= v.w;
        }
        cnt = win > 0 ? win : 1;
    }

    const float inv = 1.0f / (float)cnt;
    outRow[tid] = make_float4(acc.x * inv, acc.y * inv, acc.z * inv, acc.w * inv);
    if (Mout != nullptr && tid == 0)
        Mout[(size_t)b * maxS + s] = 1.f;
}

extern "C" void kernel_launch(void* const* d_in, const int* in_sizes, int n_in,
                              void* d_out, int out_size)
{
    const float* H    = (const float*)d_in[0];
    const float* lens = (const float*)d_in[1];
    float* out        = (float*)d_out;

    const int B = in_sizes[1];  // 32

    // Infer maxS and mask presence from out_size (768, 769 coprime; maxS << 768).
    int maxS;
    bool has_mask;
    if (out_size % (B * (D_DIM + 1)) == 0) {
        maxS = out_size / (B * (D_DIM + 1));
        has_mask = true;
    } else {
        maxS = out_size / (B * D_DIM);
        has_mask = false;
    }

    float* Mout = has_mask ? (out + (size_t)B * maxS * D_DIM) : nullptr;

    dim3 grid1(PG, B);
    piece_sum_kernel<<<grid1, NTHREADS>>>(H, lens);

    dim3 grid2(maxS, B);
    seg_out_kernel<<<grid2, NTHREADS>>>(H, out, Mout, maxS);
}

// round 6
// speedup vs baseline: 1.1212x; 1.1212x over previous
#include <cuda_runtime.h>
#include <cuda_bf16.h>

// SegmentalEmotion: per-sample sliding-window segment means (2-kernel).
// H: [B, T, D] fp32, lengths_sec: [B] fp32.
// Output: S_pad [B, maxS, D] fp32 (+ mask [B, maxS] fp32 appended, auto-detect).
//
// Reference plan (numpy fp64):
//   dur = max(len, 0.001); fps = T/dur
//   win = max(1, rint(fps)); hop = max(1, rint(fps*0.5))
//   n = (T >= win) ? (T-win)/hop + 1 : 0 ; n==0 -> fallback full-T mean
//
// The plan is recomputed per block in EXACT INTEGER arithmetic (no fp64 —
// the fp64 pipe on GB300 is 1/64-rate and per-block DDIV was measured to
// cost +4-6us chip-wide in R4/R5):
//   len = m * 2^(e-24)  (frexpf; m = 24-bit integer, exact)
//   rint(1500/len) decided by  3000*2^(24-e)  <=>  (2k+/-1)*m   (int64, exact)
//   with round-half-to-even on exact ties. fp32 divide gives the candidate k.
// Lengths outside [1, 1024) take a (never-hit-here) fp64 fallback path.
//
// Phase 1 (piece_sum): hop-chunks split into <=4 uniform pieces (~19-38
//   frames); one piece slot per block; reads H exactly once, streaming.
// Phase 2 (seg_out): 2 segments per block; window s = pieces of chunks
//   s, s+1 (+/- <=1 edge frame), scale 1/win, write output + mask.

#define T_FRAMES 1500
#define D_DIM    768
#define D_VEC    (D_DIM / 4)   // 192 float4 lanes
#define NTHREADS 192
#define MAX_B    32
#define MAX_NHOP 60            // ceil(1500/25)
#define MAX_NP   4
#define PG       80            // >= max nhop*np (78 @ hop~39)
#define PIECE_TGT 38           // target frames per piece

// piece sums: P[b, j, p, :]
__device__ float g_P[(size_t)MAX_B * MAX_NHOP * MAX_NP * D_DIM];

struct Plan { int win, hop, n_eff, nhop, np, plen, fallback; };

// rint(num/len) via exact int64 comparisons. lhs = 2*num * 2^(24-e),
// m = 24-bit mantissa of len, k = fp32 candidate (within +-1 of truth).
__device__ __forceinline__ int rint_ratio_exact(long long lhs, long long m, int k)
{
    while (lhs > (2LL * k + 1) * m) ++k;   // x > k+0.5
    while (lhs < (2LL * k - 1) * m) --k;   // x < k-0.5
    if (lhs == (2LL * k + 1) * m) return k + (k & 1);  // tie at k+0.5 -> even
    if (lhs == (2LL * k - 1) * m) return k - (k & 1);  // tie at k-0.5 -> even
    return k;
}

// Integer-exact plan. Call from ONE thread per block.
__device__ __forceinline__ Plan compute_plan(float len)
{
    Plan p;
    int win, hop;
    long long n;
    if (len >= 1.0f && len < 1024.0f) {
        // ---- fast integer path (no fp64) ----
        int e;
        float mf = frexpf(len, &e);                       // len = mf*2^e
        long long m = (long long)(mf * 16777216.0f);      // mf*2^24, exact int
        const int sh = 24 - e;                            // in [14, 23]
        win = rint_ratio_exact(3000LL << sh, m, (int)lrintf(1500.0f / len));
        hop = rint_ratio_exact(1500LL << sh, m, (int)lrintf(750.0f / len));
        if (win < 1) win = 1;
        if (hop < 1) hop = 1;
        n = (T_FRAMES >= win) ? (long long)(T_FRAMES - win) / hop + 1 : 0;
    } else {
        // ---- exact fp64 replica (never taken for len in [5,30)) ----
        double dur = fmax((double)len, 0.001);
        double fps = (double)T_FRAMES / dur;
        long long w64 = llrint(fps);       if (w64 < 1) w64 = 1;
        long long h64 = llrint(fps * 0.5); if (h64 < 1) h64 = 1;
        n = ((long long)T_FRAMES >= w64)
                ? ((long long)T_FRAMES - w64) / h64 + 1 : 0;
        if (w64 > T_FRAMES + 1) w64 = T_FRAMES + 1;
        if (h64 > T_FRAMES) h64 = T_FRAMES;
        win = (int)w64;
        hop = (int)h64;
    }
    p.fallback = (n == 0);
    p.win   = win;
    p.hop   = hop;
    p.n_eff = (int)(p.fallback ? 1 : n);
    p.nhop  = (T_FRAMES + hop - 1) / hop;
    int np = (hop + PIECE_TGT - 1) / PIECE_TGT;
    if (np > MAX_NP) np = MAX_NP;
    p.np   = np;
    p.plen = (hop + np - 1) / np;
    return p;
}

// ---------- Phase 1: uniform piece sums, reads H exactly once ----------
__global__ __launch_bounds__(NTHREADS)
void piece_sum_kernel(const float* __restrict__ H,
                      const float* __restrict__ lens)
{
    const int b   = blockIdx.y;
    const int tid = threadIdx.x;

    __shared__ Plan sp;
    if (tid == 0) sp = compute_plan(lens[b]);
    __syncthreads();

    const int np      = sp.np;
    const int hop     = sp.hop;
    const int plen    = sp.plen;
    const int npieces = sp.nhop * np;

    const float4* __restrict__ Hb =
        (const float4*)H + (size_t)b * T_FRAMES * D_VEC + tid;

    // grid-stride over piece slots (single iteration for this data: npieces<=78)
    for (int m = blockIdx.x; m < npieces; m += PG) {
        const int j = m / np;
        const int p = m - j * np;

        int t0 = j * hop + p * plen;
        int chunk_end = j * hop + hop;
        if (chunk_end > T_FRAMES) chunk_end = T_FRAMES;
        int t1 = t0 + plen;
        if (t1 > chunk_end) t1 = chunk_end;

        float4 acc = make_float4(0.f, 0.f, 0.f, 0.f);
        int t = t0;
        for (; t + 8 <= t1; t += 8) {
            float4 v0 = __ldcs(&Hb[(t + 0) * D_VEC]);
            float4 v1 = __ldcs(&Hb[(t + 1) * D_VEC]);
            float4 v2 = __ldcs(&Hb[(t + 2) * D_VEC]);
            float4 v3 = __ldcs(&Hb[(t + 3) * D_VEC]);
            float4 v4 = __ldcs(&Hb[(t + 4) * D_VEC]);
            float4 v5 = __ldcs(&Hb[(t + 5) * D_VEC]);
            float4 v6 = __ldcs(&Hb[(t + 6) * D_VEC]);
            float4 v7 = __ldcs(&Hb[(t + 7) * D_VEC]);
            acc.x += v0.x + v1.x + v2.x + v3.x + v4.x + v5.x + v6.x + v7.x;
            acc.y += v0.y + v1.y + v2.y + v3.y + v4.y + v5.y + v6.y + v7.y;
            acc.z += v0.z + v1.z + v2.z + v3.z + v4.z + v5.z + v6.z + v7.z;
            acc.w += v0.w + v1.w + v2.w + v3.w + v4.w + v5.w + v6.w + v7.w;
        }
        for (; t < t1; ++t) {
            float4 v = __ldcs(&Hb[t * D_VEC]);
            acc.x += v.x; acc.y += v.y; acc.z += v.z; acc.w += v.w;
        }

        ((float4*)g_P)[(((size_t)b * MAX_NHOP + j) * MAX_NP + p) * D_VEC + tid] = acc;
    }
}

// ---------- Phase 2: two segments per block ----------
__global__ __launch_bounds__(NTHREADS)
void seg_out_kernel(const float* __restrict__ H,
                    const float* __restrict__ lens,
                    float* __restrict__ S,      // [B, maxS, D]
                    float* __restrict__ Mout,   // [B, maxS] or nullptr
                    int maxS)
{
    const int s0  = blockIdx.x * 2;
    const int b   = blockIdx.y;
    const int tid = threadIdx.x;

    __shared__ Plan sp;
    if (tid == 0) sp = compute_plan(lens[b]);
    __syncthreads();

    const int win   = sp.win;
    const int hop   = sp.hop;
    const int n_eff = sp.n_eff;
    const int nhop  = sp.nhop;
    const int np    = sp.np;

    const float4* __restrict__ Pb =
        (const float4*)g_P + (size_t)b * MAX_NHOP * MAX_NP * D_VEC + tid;
    const float4* __restrict__ Hb =
        (const float4*)H + (size_t)b * T_FRAMES * D_VEC + tid;

    // chunk sums for chunks s0, s0+1, s0+2 (each = sum of its np pieces)
    float4 csum[3];
    #pragma unroll
    for (int c = 0; c < 3; ++c) {
        float4 a = make_float4(0.f, 0.f, 0.f, 0.f);
        const int j = s0 + c;
        if (j < nhop && !sp.fallback) {
            #pragma unroll
            for (int pp = 0; pp < MAX_NP; ++pp) {
                if (pp < np) {
                    float4 v = Pb[((size_t)j * MAX_NP + pp) * D_VEC];
                    a.x += v.x; a.y += v.y; a.z += v.z; a.w += v.w;
                }
            }
        }
        csum[c] = a;
    }

    #pragma unroll
    for (int i = 0; i < 2; ++i) {
        const int s = s0 + i;
        if (s >= maxS) break;

        float4* outRow = (float4*)(S + ((size_t)b * maxS + s) * D_DIM);

        if (s >= n_eff) {
            outRow[tid] = make_float4(0.f, 0.f, 0.f, 0.f);
            if (Mout != nullptr && tid == 0)
                Mout[(size_t)b * maxS + s] = 0.f;
            continue;
        }

        float4 acc;
        int cnt;

        if (sp.fallback) {
            // sum all pieces (rare path; only s==0 valid)
            acc = make_float4(0.f, 0.f, 0.f, 0.f);
            for (int j = 0; j < nhop; ++j)
                for (int pp = 0; pp < np; ++pp) {
                    float4 v = Pb[((size_t)j * MAX_NP + pp) * D_VEC];
                    acc.x += v.x; acc.y += v.y; acc.z += v.z; acc.w += v.w;
                }
            cnt = T_FRAMES;
        } else {
            const int start = s * hop;
            const int end   = start + win;          // <= T for s < n
            const bool have2 = (s + 1) < nhop;

            acc = csum[i];
            if (have2) {
                acc.x += csum[i + 1].x; acc.y += csum[i + 1].y;
                acc.z += csum[i + 1].z; acc.w += csum[i + 1].w;
            }
            int cov_end = start + (have2 ? 2 : 1) * hop;
            if (cov_end > T_FRAMES) cov_end = T_FRAMES;

            for (int t = cov_end; t < end; ++t) {   // add missing (<=1)
                float4 v = Hb[t * D_VEC];
                acc.x += v.x; acc.y += v.y; acc.z += v.z; acc.w += v.w;
            }
            for (int t = end; t < cov_end; ++t) {   // subtract excess (<=1)
                float4 v = Hb[t * D_VEC];
                acc.x -= v.x; acc.y -= v.y; acc.z -= v.z; acc.w -= v.w;
            }
            cnt = win > 0 ? win : 1;
        }

        const float inv = 1.0f / (float)cnt;
        outRow[tid] = make_float4(acc.x * inv, acc.y * inv, acc.z * inv, acc.w * inv);
        if (Mout != nullptr && tid == 0)
            Mout[(size_t)b * maxS + s] = 1.f;
    }
}

extern "C" void kernel_launch(void* const* d_in, const int* in_sizes, int n_in,
                              void* d_out, int out_size)
{
    const float* H    = (const float*)d_in[0];
    const float* lens = (const float*)d_in[1];
    float* out        = (float*)d_out;

    const int B = in_sizes[1];  // 32

    // Infer maxS and mask presence from out_size (768, 769 coprime; maxS << 768).
    int maxS;
    bool has_mask;
    if (out_size % (B * (D_DIM + 1)) == 0) {
        maxS = out_size / (B * (D_DIM + 1));
        has_mask = true;
    } else {
        maxS = out_size / (B * D_DIM);
        has_mask = false;
    }

    float* Mout = has_mask ? (out + (size_t)B * maxS * D_DIM) : nullptr;

    dim3 grid1(PG, B);
    piece_sum_kernel<<<grid1, NTHREADS>>>(H, lens);

    dim3 grid2((maxS + 1) / 2, B);
    seg_out_kernel<<<grid2, NTHREADS>>>(H, lens, out, Mout, maxS);
}